// round 4
// baseline (speedup 1.0000x reference)
#include <cuda_runtime.h>
#include <cuda_bf16.h>

// ---------------------------------------------------------------------------
// 2-layer GCN: h = relu(GCN(relu(GCN(x, W1, b1)), W2, b2))
// GCNConv: out = D^{-1/2}(A+I)D^{-1/2} X W + b      (edge_index is int32)
//
// R4: pull-based CSR aggregation (no feature atomics), fused self-loop +
//     bias + relu in the gather epilogue. CSR built once per call, used by
//     both layers.
// ---------------------------------------------------------------------------

#define MAX_N 50000
#define MAX_E 600000
#define H 128
#define SCAN_T 1024

__device__ float g_dinv[MAX_N];
__device__ int   g_cnt[MAX_N];
__device__ int   g_off[MAX_N + 1];
__device__ int   g_cursor[MAX_N];
__device__ int   g_csr_src[MAX_E];
__device__ float g_xw[MAX_N * H];
__device__ float g_h[MAX_N * H];

// ---------------------------------------------------------------------------
// CSR build
// ---------------------------------------------------------------------------
__global__ void zero_cnt_kernel(int* cnt, int n) {
    int i = blockIdx.x * blockDim.x + threadIdx.x;
    if (i < n) cnt[i] = 0;
}

__global__ void count_kernel(const int* __restrict__ ei, int* cnt, int e) {
    int i = blockIdx.x * blockDim.x + threadIdx.x;
    if (i < e) atomicAdd(&cnt[ei[e + i]], 1);
}

// Single-block exclusive scan over n counts -> off, cursor; dinv = rsqrt(1+cnt).
__global__ void __launch_bounds__(SCAN_T) scan_kernel(
    const int* __restrict__ cnt, int* __restrict__ off,
    int* __restrict__ cursor, float* __restrict__ dinv, int n)
{
    __shared__ int part[SCAN_T];
    const int t = threadIdx.x;
    const int chunk = (n + SCAN_T - 1) / SCAN_T;
    const int beg = t * chunk;
    const int end = min(beg + chunk, n);

    int local = 0;
    for (int i = beg; i < end; i++) local += cnt[i];
    part[t] = local;
    __syncthreads();

    // Hillis-Steele inclusive scan over 1024 partials
    for (int s = 1; s < SCAN_T; s <<= 1) {
        int v = (t >= s) ? part[t - s] : 0;
        __syncthreads();
        part[t] += v;
        __syncthreads();
    }

    int run = (t == 0) ? 0 : part[t - 1];  // exclusive prefix of this chunk
    for (int i = beg; i < end; i++) {
        off[i] = run;
        cursor[i] = run;
        dinv[i] = rsqrtf(1.0f + (float)cnt[i]);
        run += cnt[i];
    }
    if (t == SCAN_T - 1) off[n] = run;
}

__global__ void fill_kernel(const int* __restrict__ ei,
                            int* __restrict__ cursor,
                            int* __restrict__ csr_src, int e)
{
    int i = blockIdx.x * blockDim.x + threadIdx.x;
    if (i < e) {
        int s = ei[i];
        int d = ei[e + i];
        int p = atomicAdd(&cursor[d], 1);
        csr_src[p] = s;
    }
}

// ---------------------------------------------------------------------------
// GEMM: xw = A @ W. Block 64 rows x 128 cols, thread tile 8x4.
// ---------------------------------------------------------------------------
__global__ void __launch_bounds__(256, 3) gemm128_kernel(
    const float* __restrict__ A, const float* __restrict__ W,
    float* __restrict__ xw, int n)
{
    __shared__ float xs[64][H];    // 32 KB
    __shared__ float ws[32][H];    // 16 KB

    const int tid = threadIdx.x;
    const int row0 = blockIdx.x * 64;

    const float4* A4 = reinterpret_cast<const float4*>(A);
#pragma unroll
    for (int i = tid; i < 64 * 32; i += 256) {
        int r = i >> 5, c4 = i & 31;
        int row = row0 + r;
        float4 v = make_float4(0.f, 0.f, 0.f, 0.f);
        if (row < n) v = A4[row * 32 + c4];
        reinterpret_cast<float4*>(&xs[r][0])[c4] = v;
    }

    const int tx = tid & 31;
    const int ty = tid >> 5;

    float acc[8][4];
#pragma unroll
    for (int r = 0; r < 8; r++)
#pragma unroll
        for (int c = 0; c < 4; c++) acc[r][c] = 0.f;

    const float4* W4 = reinterpret_cast<const float4*>(W);

#pragma unroll 1
    for (int kc = 0; kc < 4; kc++) {
        __syncthreads();
#pragma unroll
        for (int i = tid; i < 32 * 32; i += 256) {
            int r = i >> 5, c4 = i & 31;
            reinterpret_cast<float4*>(&ws[r][0])[c4] = W4[(kc * 32 + r) * 32 + c4];
        }
        __syncthreads();

#pragma unroll
        for (int k = 0; k < 32; k++) {
            float4 w4 = reinterpret_cast<float4*>(&ws[k][0])[tx];
            float a[8];
#pragma unroll
            for (int r = 0; r < 8; r++) a[r] = xs[ty * 8 + r][kc * 32 + k];
#pragma unroll
            for (int r = 0; r < 8; r++) {
                acc[r][0] += a[r] * w4.x;
                acc[r][1] += a[r] * w4.y;
                acc[r][2] += a[r] * w4.z;
                acc[r][3] += a[r] * w4.w;
            }
        }
    }

#pragma unroll
    for (int r = 0; r < 8; r++) {
        int row = row0 + ty * 8 + r;
        if (row < n) {
            float4 v = make_float4(acc[r][0], acc[r][1], acc[r][2], acc[r][3]);
            reinterpret_cast<float4*>(xw + (size_t)row * H)[tx] = v;
        }
    }
}

// ---------------------------------------------------------------------------
// Pull aggregation: one warp per node.
//   out[d] = relu( dinv[d] * ( sum_{s in N(d)} dinv[s]*xw[s] + dinv[d]*xw[d] ) + b )
// Each lane owns one float4 (4 columns). Neighbor reads are fully coalesced
// (32 lanes x 16B = one 512B row). csr/dinv reads are warp-uniform broadcasts.
// ---------------------------------------------------------------------------
__global__ void __launch_bounds__(256) gather_kernel(
    const int* __restrict__ csr_src,
    const int* __restrict__ off,
    const float* __restrict__ dinv,
    const float* __restrict__ xw,
    const float* __restrict__ b,
    float* __restrict__ out, int n)
{
    int node = (blockIdx.x * blockDim.x + threadIdx.x) >> 5;
    int lane = threadIdx.x & 31;
    if (node >= n) return;

    const float4* xw4 = reinterpret_cast<const float4*>(xw);
    int j   = off[node];
    int end = off[node + 1];

    float4 acc0 = make_float4(0.f, 0.f, 0.f, 0.f);
    float4 acc1 = make_float4(0.f, 0.f, 0.f, 0.f);

    // Unroll by 2 with independent accumulators to double in-flight gathers.
    for (; j + 1 < end; j += 2) {
        int s0 = csr_src[j];
        int s1 = csr_src[j + 1];
        float d0 = dinv[s0];
        float d1 = dinv[s1];
        float4 v0 = xw4[(size_t)s0 * 32 + lane];
        float4 v1 = xw4[(size_t)s1 * 32 + lane];
        acc0.x += d0 * v0.x; acc0.y += d0 * v0.y;
        acc0.z += d0 * v0.z; acc0.w += d0 * v0.w;
        acc1.x += d1 * v1.x; acc1.y += d1 * v1.y;
        acc1.z += d1 * v1.z; acc1.w += d1 * v1.w;
    }
    if (j < end) {
        int s0 = csr_src[j];
        float d0 = dinv[s0];
        float4 v0 = xw4[(size_t)s0 * 32 + lane];
        acc0.x += d0 * v0.x; acc0.y += d0 * v0.y;
        acc0.z += d0 * v0.z; acc0.w += d0 * v0.w;
    }

    float dd = dinv[node];
    float4 xv = xw4[(size_t)node * 32 + lane];
    float4 bb = reinterpret_cast<const float4*>(b)[lane];

    float4 r;
    r.x = fmaxf(dd * (acc0.x + acc1.x + dd * xv.x) + bb.x, 0.f);
    r.y = fmaxf(dd * (acc0.y + acc1.y + dd * xv.y) + bb.y, 0.f);
    r.z = fmaxf(dd * (acc0.z + acc1.z + dd * xv.z) + bb.z, 0.f);
    r.w = fmaxf(dd * (acc0.w + acc1.w + dd * xv.w) + bb.w, 0.f);
    reinterpret_cast<float4*>(out)[(size_t)node * 32 + lane] = r;
}

// ---------------------------------------------------------------------------
// Launch
// ---------------------------------------------------------------------------
extern "C" void kernel_launch(void* const* d_in, const int* in_sizes, int n_in,
                              void* d_out, int out_size)
{
    const float* x  = (const float*)d_in[0];
    const int*   ei = (const int*)d_in[1];
    const float* W1 = (const float*)d_in[2];
    const float* b1 = (const float*)d_in[3];
    const float* W2 = (const float*)d_in[4];
    const float* b2 = (const float*)d_in[5];
    float* out = (float*)d_out;

    const int n = in_sizes[0] / H;       // 50000
    const int e = in_sizes[1] / 2;       // 600000

    float* dinv;   cudaGetSymbolAddress((void**)&dinv,   g_dinv);
    int*   cnt;    cudaGetSymbolAddress((void**)&cnt,    g_cnt);
    int*   off;    cudaGetSymbolAddress((void**)&off,    g_off);
    int*   cursor; cudaGetSymbolAddress((void**)&cursor, g_cursor);
    int*   csr;    cudaGetSymbolAddress((void**)&csr,    g_csr_src);
    float* xw;     cudaGetSymbolAddress((void**)&xw,     g_xw);
    float* h;      cudaGetSymbolAddress((void**)&h,      g_h);

    const int T = 256;
    const int blocks_n    = (n + T - 1) / T;
    const int blocks_e    = (e + T - 1) / T;
    const int blocks_gemm = (n + 63) / 64;
    const int blocks_gath = (n * 32 + T - 1) / T;   // warp per node

    // CSR build (shared by both layers)
    zero_cnt_kernel<<<blocks_n, T>>>(cnt, n);
    count_kernel<<<blocks_e, T>>>(ei, cnt, e);
    scan_kernel<<<1, SCAN_T>>>(cnt, off, cursor, dinv, n);
    fill_kernel<<<blocks_e, T>>>(ei, cursor, csr, e);

    // layer 1
    gemm128_kernel<<<blocks_gemm, T>>>(x, W1, xw, n);
    gather_kernel<<<blocks_gath, T>>>(csr, off, dinv, xw, b1, h, n);

    // layer 2
    gemm128_kernel<<<blocks_gemm, T>>>(h, W2, xw, n);
    gather_kernel<<<blocks_gath, T>>>(csr, off, dinv, xw, b2, out, n);
}